// round 2
// baseline (speedup 1.0000x reference)
#include <cuda_runtime.h>
#include <math.h>

#define BB 4
#define SS 4096
#define DD 1024
#define MM (BB * SS)   // 16384

// Scratch (alloc-free rule: __device__ globals)
__device__ float g_q[(size_t)MM * DD];            // 64 MB
__device__ float g_k[(size_t)MM * DD];            // 64 MB
__device__ float g_v[(size_t)MM * DD];            // 64 MB
__device__ float g_p[(size_t)BB * SS * SS];       // 256 MB (scores / weights)

// ---------------------------------------------------------------------------
// QKV projection: O[m, n] = sum_d X[m, d] * W[n, d]   (x @ W^T, NT GEMM)
// 64x64 tile, BK=16, 256 threads, 4x4 per thread.
// ---------------------------------------------------------------------------
__global__ __launch_bounds__(256) void proj_kernel(
    const float* __restrict__ X,
    const float* __restrict__ Wq,
    const float* __restrict__ Wk,
    const float* __restrict__ Wv)
{
    __shared__ float As[16][64];
    __shared__ float Bs[16][64];

    const float* W = (blockIdx.z == 0) ? Wq : (blockIdx.z == 1) ? Wk : Wv;
    float* O       = (blockIdx.z == 0) ? g_q : (blockIdx.z == 1) ? g_k : g_v;

    const int m0 = blockIdx.x * 64;
    const int n0 = blockIdx.y * 64;
    const int t  = threadIdx.x;
    const int tx = t & 15, ty = t >> 4;
    const int lrow = t >> 2, lc4 = t & 3;   // loader: 64 rows x 4 float4 cols

    float c[4][4] = {};

    for (int k0 = 0; k0 < DD; k0 += 16) {
        float4 av = *(const float4*)&X[(size_t)(m0 + lrow) * DD + k0 + lc4 * 4];
        float4 bv = *(const float4*)&W[(size_t)(n0 + lrow) * DD + k0 + lc4 * 4];
        As[lc4 * 4 + 0][lrow] = av.x; As[lc4 * 4 + 1][lrow] = av.y;
        As[lc4 * 4 + 2][lrow] = av.z; As[lc4 * 4 + 3][lrow] = av.w;
        Bs[lc4 * 4 + 0][lrow] = bv.x; Bs[lc4 * 4 + 1][lrow] = bv.y;
        Bs[lc4 * 4 + 2][lrow] = bv.z; Bs[lc4 * 4 + 3][lrow] = bv.w;
        __syncthreads();

        #pragma unroll
        for (int kk = 0; kk < 16; kk++) {
            float4 a = *(const float4*)&As[kk][ty * 4];
            float4 b = *(const float4*)&Bs[kk][tx * 4];
            c[0][0] += a.x * b.x; c[0][1] += a.x * b.y; c[0][2] += a.x * b.z; c[0][3] += a.x * b.w;
            c[1][0] += a.y * b.x; c[1][1] += a.y * b.y; c[1][2] += a.y * b.z; c[1][3] += a.y * b.w;
            c[2][0] += a.z * b.x; c[2][1] += a.z * b.y; c[2][2] += a.z * b.z; c[2][3] += a.z * b.w;
            c[3][0] += a.w * b.x; c[3][1] += a.w * b.y; c[3][2] += a.w * b.z; c[3][3] += a.w * b.w;
        }
        __syncthreads();
    }

    #pragma unroll
    for (int i = 0; i < 4; i++) {
        float4 v = make_float4(c[i][0], c[i][1], c[i][2], c[i][3]);
        *(float4*)&O[(size_t)(m0 + ty * 4 + i) * DD + n0 + tx * 4] = v;
    }
}

// ---------------------------------------------------------------------------
// Scores: P[b, q, k] = (Q[b,q,:] . K[b,k,:]) / 32   (only tiles with k0 <= q0)
// ---------------------------------------------------------------------------
__global__ __launch_bounds__(256) void scores_kernel()
{
    if (blockIdx.y > blockIdx.x) return;  // strictly upper tile: skip entirely

    __shared__ float As[16][64];
    __shared__ float Bs[16][64];

    const int b  = blockIdx.z;
    const int q0 = blockIdx.x * 64;
    const int k0t = blockIdx.y * 64;
    const float* Q = g_q + (size_t)b * SS * DD;
    const float* K = g_k + (size_t)b * SS * DD;
    float* P       = g_p + (size_t)b * SS * SS;

    const int t  = threadIdx.x;
    const int tx = t & 15, ty = t >> 4;
    const int lrow = t >> 2, lc4 = t & 3;

    float c[4][4] = {};

    for (int d0 = 0; d0 < DD; d0 += 16) {
        float4 av = *(const float4*)&Q[(size_t)(q0  + lrow) * DD + d0 + lc4 * 4];
        float4 bv = *(const float4*)&K[(size_t)(k0t + lrow) * DD + d0 + lc4 * 4];
        As[lc4 * 4 + 0][lrow] = av.x; As[lc4 * 4 + 1][lrow] = av.y;
        As[lc4 * 4 + 2][lrow] = av.z; As[lc4 * 4 + 3][lrow] = av.w;
        Bs[lc4 * 4 + 0][lrow] = bv.x; Bs[lc4 * 4 + 1][lrow] = bv.y;
        Bs[lc4 * 4 + 2][lrow] = bv.z; Bs[lc4 * 4 + 3][lrow] = bv.w;
        __syncthreads();

        #pragma unroll
        for (int kk = 0; kk < 16; kk++) {
            float4 a = *(const float4*)&As[kk][ty * 4];
            float4 b2 = *(const float4*)&Bs[kk][tx * 4];
            c[0][0] += a.x * b2.x; c[0][1] += a.x * b2.y; c[0][2] += a.x * b2.z; c[0][3] += a.x * b2.w;
            c[1][0] += a.y * b2.x; c[1][1] += a.y * b2.y; c[1][2] += a.y * b2.z; c[1][3] += a.y * b2.w;
            c[2][0] += a.z * b2.x; c[2][1] += a.z * b2.y; c[2][2] += a.z * b2.z; c[2][3] += a.z * b2.w;
            c[3][0] += a.w * b2.x; c[3][1] += a.w * b2.y; c[3][2] += a.w * b2.z; c[3][3] += a.w * b2.w;
        }
        __syncthreads();
    }

    const float scale = 0.03125f;  // 1/sqrt(1024)
    #pragma unroll
    for (int i = 0; i < 4; i++) {
        float4 v = make_float4(c[i][0] * scale, c[i][1] * scale,
                               c[i][2] * scale, c[i][3] * scale);
        *(float4*)&P[(size_t)(q0 + ty * 4 + i) * SS + k0t + tx * 4] = v;
    }
}

// ---------------------------------------------------------------------------
// Row softmax over k in [0, q]; zero the strict upper tail so PV reads zeros.
// ---------------------------------------------------------------------------
__global__ __launch_bounds__(256) void softmax_kernel()
{
    const int q = blockIdx.x;
    const int b = blockIdx.y;
    float* row = g_p + (size_t)b * SS * SS + (size_t)q * SS;
    const int len = q + 1;
    const int t = threadIdx.x;

    __shared__ float red[256];

    float m = -INFINITY;
    for (int k = t; k < len; k += 256) m = fmaxf(m, row[k]);
    red[t] = m; __syncthreads();
    for (int s = 128; s > 0; s >>= 1) {
        if (t < s) red[t] = fmaxf(red[t], red[t + s]);
        __syncthreads();
    }
    m = red[0];
    __syncthreads();

    float sum = 0.0f;
    for (int k = t; k < len; k += 256) {
        float e = __expf(row[k] - m);
        row[k] = e;
        sum += e;
    }
    red[t] = sum; __syncthreads();
    for (int s = 128; s > 0; s >>= 1) {
        if (t < s) red[t] += red[t + s];
        __syncthreads();
    }
    const float inv = 1.0f / red[0];

    for (int k = t; k < len; k += 256) row[k] *= inv;
    for (int k = len + t; k < SS; k += 256) row[k] = 0.0f;  // strict upper: zero
}

// ---------------------------------------------------------------------------
// Output: O[b, q, e] = sum_{k <= q} P[b,q,k] * V[b,k,e]  (NN GEMM, clamped k)
// ---------------------------------------------------------------------------
__global__ __launch_bounds__(256) void pv_kernel(float* __restrict__ out)
{
    __shared__ float As[16][64];
    __shared__ float Bs[16][64];

    const int b  = blockIdx.z;
    const int q0 = blockIdx.x * 64;
    const int e0 = blockIdx.y * 64;
    const float* P = g_p + (size_t)b * SS * SS;
    const float* V = g_v + (size_t)b * SS * DD;

    const int t  = threadIdx.x;
    const int tx = t & 15, ty = t >> 4;
    const int arow = t >> 2, ac4 = t & 3;    // A loader: 64 rows x 4 float4
    const int brow = t >> 4, bc4 = t & 15;   // B loader: 16 rows x 16 float4

    float c[4][4] = {};

    const int kmax = q0 + 64;  // exclusive; P[q, k>q] == 0 so diagonal tile is safe

    for (int k0 = 0; k0 < kmax; k0 += 16) {
        float4 av = *(const float4*)&P[(size_t)(q0 + arow) * SS + k0 + ac4 * 4];
        float4 bv = *(const float4*)&V[(size_t)(k0 + brow) * DD + e0 + bc4 * 4];
        As[ac4 * 4 + 0][arow] = av.x; As[ac4 * 4 + 1][arow] = av.y;
        As[ac4 * 4 + 2][arow] = av.z; As[ac4 * 4 + 3][arow] = av.w;
        *(float4*)&Bs[brow][bc4 * 4] = bv;
        __syncthreads();

        #pragma unroll
        for (int kk = 0; kk < 16; kk++) {
            float4 a  = *(const float4*)&As[kk][ty * 4];
            float4 b2 = *(const float4*)&Bs[kk][tx * 4];
            c[0][0] += a.x * b2.x; c[0][1] += a.x * b2.y; c[0][2] += a.x * b2.z; c[0][3] += a.x * b2.w;
            c[1][0] += a.y * b2.x; c[1][1] += a.y * b2.y; c[1][2] += a.y * b2.z; c[1][3] += a.y * b2.w;
            c[2][0] += a.z * b2.x; c[2][1] += a.z * b2.y; c[2][2] += a.z * b2.z; c[2][3] += a.z * b2.w;
            c[3][0] += a.w * b2.x; c[3][1] += a.w * b2.y; c[3][2] += a.w * b2.z; c[3][3] += a.w * b2.w;
        }
        __syncthreads();
    }

    #pragma unroll
    for (int i = 0; i < 4; i++) {
        float4 v = make_float4(c[i][0], c[i][1], c[i][2], c[i][3]);
        *(float4*)&out[(size_t)(b * SS + q0 + ty * 4 + i) * DD + e0 + tx * 4] = v;
    }
}

// ---------------------------------------------------------------------------
extern "C" void kernel_launch(void* const* d_in, const int* in_sizes, int n_in,
                              void* d_out, int out_size)
{
    const float* X  = (const float*)d_in[0];
    const float* Wq = (const float*)d_in[1];
    const float* Wk = (const float*)d_in[2];
    const float* Wv = (const float*)d_in[3];
    float* out      = (float*)d_out;

    dim3 g1(MM / 64, DD / 64, 3);
    proj_kernel<<<g1, 256>>>(X, Wq, Wk, Wv);

    dim3 g2(SS / 64, SS / 64, BB);
    scores_kernel<<<g2, 256>>>();

    dim3 g3(SS, BB);
    softmax_kernel<<<g3, 256>>>();

    dim3 g4(SS / 64, DD / 64, BB);
    pv_kernel<<<g4, 256>>>(out);
}

// round 5
// speedup vs baseline: 3.7785x; 3.7785x over previous
#include <cuda_runtime.h>
#include <cuda_bf16.h>
#include <cstdint>
#include <math.h>

#define BB 4
#define SS 4096
#define DD 1024
#define MM (BB * SS)   // 16384

// ---------------------------------------------------------------------------
// Scratch (__device__ globals; alloc-free rule)
// ---------------------------------------------------------------------------
__device__ __align__(256) __nv_bfloat16 g_xh[(size_t)MM * DD];
__device__ __align__(256) __nv_bfloat16 g_xl[(size_t)MM * DD];
__device__ __align__(256) __nv_bfloat16 g_wh[(size_t)3 * DD * DD];
__device__ __align__(256) __nv_bfloat16 g_wl[(size_t)3 * DD * DD];
__device__ __align__(256) __nv_bfloat16 g_qh[(size_t)MM * DD];
__device__ __align__(256) __nv_bfloat16 g_ql[(size_t)MM * DD];
__device__ __align__(256) __nv_bfloat16 g_kh[(size_t)MM * DD];
__device__ __align__(256) __nv_bfloat16 g_kl[(size_t)MM * DD];
__device__ __align__(256) __nv_bfloat16 g_vth[(size_t)MM * DD];  // [b][e][s]
__device__ __align__(256) __nv_bfloat16 g_vtl[(size_t)MM * DD];  // [b][e][s]
__device__ __align__(256) float         g_p [(size_t)BB * SS * SS]; // fp32 scores
__device__ __align__(256) __nv_bfloat16 g_ph[(size_t)BB * SS * SS]; // softmax hi
__device__ __align__(256) __nv_bfloat16 g_pl[(size_t)BB * SS * SS]; // softmax lo

// ---------------------------------------------------------------------------
// PTX helpers (sm_80-era PTX only: cp.async, ldmatrix, mma.sync — no tcgen05)
// ---------------------------------------------------------------------------
__device__ __forceinline__ uint32_t smem_u32(const void* p) {
    uint32_t a;
    asm("{ .reg .u64 t; cvta.to.shared.u64 t, %1; cvt.u32.u64 %0, t; }"
        : "=r"(a) : "l"(p));
    return a;
}

#define LDSM4(r0, r1, r2, r3, addr) \
    asm volatile("ldmatrix.sync.aligned.m8n8.x4.shared.b16 {%0,%1,%2,%3}, [%4];" \
                 : "=r"(r0), "=r"(r1), "=r"(r2), "=r"(r3) : "r"(addr))

__device__ __forceinline__ void mma_bf16(float* c, const uint32_t* a,
                                         uint32_t b0, uint32_t b1) {
    asm volatile(
        "mma.sync.aligned.m16n8k16.row.col.f32.bf16.bf16.f32 "
        "{%0,%1,%2,%3}, {%4,%5,%6,%7}, {%8,%9}, {%0,%1,%2,%3};"
        : "+f"(c[0]), "+f"(c[1]), "+f"(c[2]), "+f"(c[3])
        : "r"(a[0]), "r"(a[1]), "r"(a[2]), "r"(a[3]), "r"(b0), "r"(b1));
}

template <int N>
__device__ __forceinline__ void cp_wait() {
    asm volatile("cp.async.wait_group %0;" :: "n"(N) : "memory");
}
__device__ __forceinline__ void cp_commit() {
    asm volatile("cp.async.commit_group;" ::: "memory");
}

// smem stage layout: 4 tiles of 128 rows x 64 bf16 (128B rows, SW128 swizzle)
#define TILE_SZ  16384
#define T_AH     0
#define T_AL     16384
#define T_BH     32768
#define T_BL     49152
#define STAGE_SZ 65536
#define SMEM_BYTES (2 * STAGE_SZ)

__device__ __forceinline__ uint32_t sw_off(int r, int cbyte) {
    uint32_t off = (uint32_t)(r * 128 + cbyte);
    return off ^ ((off >> 3) & 0x70);
}

// Load one 128x64-bf16 tile (K-contiguous source) into swizzled smem via cp.async.
__device__ __forceinline__ void cp_tile(uint32_t sdst,
                                        const __nv_bfloat16* __restrict__ g,
                                        size_t row0, int ldk, int k0) {
    const int t = threadIdx.x;
    const char* gb = (const char*)(g + row0 * (size_t)ldk + (size_t)k0);
    #pragma unroll
    for (int i = 0; i < 4; i++) {
        int u = t + i * 256;            // 0..1023
        int r = u >> 3, cb = (u & 7) * 16;
        const char* src = gb + (size_t)r * (size_t)ldk * 2 + cb;
        asm volatile("cp.async.cg.shared.global [%0], [%1], 16;"
                     :: "r"(sdst + sw_off(r, cb)), "l"(src) : "memory");
    }
}

// ---------------------------------------------------------------------------
// Compute one BK=64 chunk: C += (Ah+Al)(128x64) @ (Bh+Bl)(128x64)^T (3 passes)
// ---------------------------------------------------------------------------
__device__ __forceinline__ void compute_chunk(uint32_t stage, float C[16][4]) {
    const int lane = threadIdx.x & 31;
    const int wid  = threadIdx.x >> 5;
    const int wm = wid & 1;   // 0/1: 64-row half
    const int wn = wid >> 1;  // 0..3: 32-col quarter

    uint32_t ah[4][4], al[4][4], bh[4][4], bl[4][4];

    #pragma unroll
    for (int ks = 0; ks < 4; ks++) {
        if ((ks & 1) == 0) {
            #pragma unroll
            for (int n = 0; n < 4; n++) {
                int r  = wn * 32 + n * 8 + (lane & 7);
                int cb = ks * 32 + (lane >> 3) * 16;
                uint32_t o = sw_off(r, cb);
                LDSM4(bh[n][0], bh[n][1], bh[n][2], bh[n][3], stage + T_BH + o);
                LDSM4(bl[n][0], bl[n][1], bl[n][2], bl[n][3], stage + T_BL + o);
            }
        }
        #pragma unroll
        for (int am = 0; am < 4; am++) {
            int r  = wm * 64 + am * 16 + (lane & 15);
            int cb = ks * 32 + (lane >> 4) * 16;
            uint32_t o = sw_off(r, cb);
            LDSM4(ah[am][0], ah[am][1], ah[am][2], ah[am][3], stage + T_AH + o);
            LDSM4(al[am][0], al[am][1], al[am][2], al[am][3], stage + T_AL + o);
        }
        const int kp = (ks & 1) * 2;
        #pragma unroll
        for (int am = 0; am < 4; am++) {
            #pragma unroll
            for (int n = 0; n < 4; n++) {
                float* c = C[am * 4 + n];
                mma_bf16(c, ah[am], bh[n][kp], bh[n][kp + 1]);
                mma_bf16(c, ah[am], bl[n][kp], bl[n][kp + 1]);
                mma_bf16(c, al[am], bh[n][kp], bh[n][kp + 1]);
            }
        }
    }
}

// ---------------------------------------------------------------------------
// 128x128 NT GEMM tile: C = (Ah+Al)[128,K] @ (Bh+Bl)[128,K]^T, K = nch*64
// ---------------------------------------------------------------------------
__device__ __forceinline__ void gemm_tile(
    char* smem,
    const __nv_bfloat16* __restrict__ Ah, const __nv_bfloat16* __restrict__ Al,
    size_t arow0, int lda,
    const __nv_bfloat16* __restrict__ Bh, const __nv_bfloat16* __restrict__ Bl,
    size_t brow0, int ldb,
    int nch, float C[16][4])
{
    const uint32_t sb = smem_u32(smem);

    #pragma unroll
    for (int i = 0; i < 16; i++)
        #pragma unroll
        for (int j = 0; j < 4; j++) C[i][j] = 0.0f;

    cp_tile(sb + T_AH, Ah, arow0, lda, 0);
    cp_tile(sb + T_AL, Al, arow0, lda, 0);
    cp_tile(sb + T_BH, Bh, brow0, ldb, 0);
    cp_tile(sb + T_BL, Bl, brow0, ldb, 0);
    cp_commit();

    for (int c = 0; c < nch; c++) {
        if (c + 1 < nch) {
            const uint32_t ns = sb + ((c + 1) & 1) * STAGE_SZ;
            const int k0 = (c + 1) * 64;
            cp_tile(ns + T_AH, Ah, arow0, lda, k0);
            cp_tile(ns + T_AL, Al, arow0, lda, k0);
            cp_tile(ns + T_BH, Bh, brow0, ldb, k0);
            cp_tile(ns + T_BL, Bl, brow0, ldb, k0);
            cp_commit();
            cp_wait<1>();
        } else {
            cp_wait<0>();
        }
        __syncthreads();
        compute_chunk(sb + (c & 1) * STAGE_SZ, C);
        __syncthreads();
    }
}

// C fragment coords: rows gr, gr+8; cols gc, gc+1
#define FRAG_COORDS() \
    const int lane = threadIdx.x & 31; \
    const int wid  = threadIdx.x >> 5; \
    const int wm = wid & 1, wn = wid >> 1;

// ---------------------------------------------------------------------------
// Split fp32 -> bf16 hi/lo. mode: 0 -> X, 1..3 -> W[z]
// ---------------------------------------------------------------------------
__global__ __launch_bounds__(256) void split_kernel(
    const float* __restrict__ src, int mode, int n4)
{
    int i = blockIdx.x * 256 + threadIdx.x;
    if (i >= n4) return;
    __nv_bfloat16* h;
    __nv_bfloat16* l;
    if (mode == 0) { h = g_xh; l = g_xl; }
    else { h = g_wh + (size_t)(mode - 1) * DD * DD; l = g_wl + (size_t)(mode - 1) * DD * DD; }
    float4 v = ((const float4*)src)[i];
    __nv_bfloat16 h0 = __float2bfloat16(v.x), h1 = __float2bfloat16(v.y);
    __nv_bfloat16 h2 = __float2bfloat16(v.z), h3 = __float2bfloat16(v.w);
    __nv_bfloat162 a, b;
    a.x = h0; a.y = h1; b.x = h2; b.y = h3;
    ((__nv_bfloat162*)h)[2 * i] = a; ((__nv_bfloat162*)h)[2 * i + 1] = b;
    a.x = __float2bfloat16(v.x - __bfloat162float(h0));
    a.y = __float2bfloat16(v.y - __bfloat162float(h1));
    b.x = __float2bfloat16(v.z - __bfloat162float(h2));
    b.y = __float2bfloat16(v.w - __bfloat162float(h3));
    ((__nv_bfloat162*)l)[2 * i] = a; ((__nv_bfloat162*)l)[2 * i + 1] = b;
}

// ---------------------------------------------------------------------------
// Projection: z=0 Q, z=1 K (bf16 hi/lo out), z=2 V (bf16 hi/lo transposed out)
// ---------------------------------------------------------------------------
__global__ __launch_bounds__(256, 1) void proj_kernel()
{
    extern __shared__ char smem[];
    const int z = blockIdx.z;
    const size_t m0 = (size_t)blockIdx.x * 128;
    const int n0 = blockIdx.y * 128;

    float C[16][4];
    gemm_tile(smem,
              g_xh, g_xl, m0, DD,
              g_wh + (size_t)z * DD * DD, g_wl + (size_t)z * DD * DD, (size_t)n0, DD,
              DD / 64, C);

    FRAG_COORDS();
    if (z < 2) {
        __nv_bfloat16* H = (z == 0) ? g_qh : g_kh;
        __nv_bfloat16* L = (z == 0) ? g_ql : g_kl;
        #pragma unroll
        for (int am = 0; am < 4; am++) {
            #pragma unroll
            for (int n = 0; n < 4; n++) {
                const float* c = C[am * 4 + n];
                const int gr = wm * 64 + am * 16 + (lane >> 2);
                const int gc = n0 + wn * 32 + n * 8 + (lane & 3) * 2;
                #pragma unroll
                for (int half = 0; half < 2; half++) {
                    float f0 = c[half * 2], f1 = c[half * 2 + 1];
                    __nv_bfloat16 h0 = __float2bfloat16(f0);
                    __nv_bfloat16 h1 = __float2bfloat16(f1);
                    __nv_bfloat162 hv, lv;
                    hv.x = h0; hv.y = h1;
                    lv.x = __float2bfloat16(f0 - __bfloat162float(h0));
                    lv.y = __float2bfloat16(f1 - __bfloat162float(h1));
                    size_t a = (m0 + (size_t)(gr + half * 8)) * DD + gc;
                    *(__nv_bfloat162*)(H + a) = hv;
                    *(__nv_bfloat162*)(L + a) = lv;
                }
            }
        }
    } else {
        const int b = (int)(m0 >> 12);
        const int sbase = (int)(m0 & (SS - 1));
        #pragma unroll
        for (int am = 0; am < 4; am++) {
            #pragma unroll
            for (int n = 0; n < 4; n++) {
                const float* c = C[am * 4 + n];
                const int gr = wm * 64 + am * 16 + (lane >> 2);
                const int gc = n0 + wn * 32 + n * 8 + (lane & 3) * 2;
                #pragma unroll
                for (int j = 0; j < 4; j++) {
                    const int s = sbase + gr + (j >> 1) * 8;   // row
                    const int e = gc + (j & 1);                // col
                    float f = c[j];
                    __nv_bfloat16 hh = __float2bfloat16(f);
                    size_t a = ((size_t)b * DD + e) * SS + s;
                    g_vth[a] = hh;
                    g_vtl[a] = __float2bfloat16(f - __bfloat162float(hh));
                }
            }
        }
    }
}

// ---------------------------------------------------------------------------
// Scores: P[b,q,k] = (Q.K)/32, causal tile skip
// ---------------------------------------------------------------------------
__global__ __launch_bounds__(256, 1) void scores_kernel()
{
    if (blockIdx.y > blockIdx.x) return;
    extern __shared__ char smem[];
    const int b = blockIdx.z;
    const size_t q0 = (size_t)blockIdx.x * 128;
    const size_t k0 = (size_t)blockIdx.y * 128;

    float C[16][4];
    gemm_tile(smem,
              g_qh + (size_t)b * SS * DD, g_ql + (size_t)b * SS * DD, q0, DD,
              g_kh + (size_t)b * SS * DD, g_kl + (size_t)b * SS * DD, k0, DD,
              DD / 64, C);

    FRAG_COORDS();
    float* P = g_p + (size_t)b * SS * SS;
    const float scale = 0.03125f;  // 1/sqrt(1024)
    #pragma unroll
    for (int am = 0; am < 4; am++) {
        #pragma unroll
        for (int n = 0; n < 4; n++) {
            const float* c = C[am * 4 + n];
            const int gr = wm * 64 + am * 16 + (lane >> 2);
            const int gc = (int)k0 + wn * 32 + n * 8 + (lane & 3) * 2;
            float2 v0 = make_float2(c[0] * scale, c[1] * scale);
            float2 v1 = make_float2(c[2] * scale, c[3] * scale);
            *(float2*)(P + (q0 + (size_t)gr) * SS + gc) = v0;
            *(float2*)(P + (q0 + (size_t)gr + 8) * SS + gc) = v1;
        }
    }
}

// ---------------------------------------------------------------------------
// Softmax over k in [0,q]; emit bf16 hi/lo weights; zero tail to 128-tile edge
// ---------------------------------------------------------------------------
__global__ __launch_bounds__(256) void softmax_kernel()
{
    const int q = blockIdx.x;
    const int b = blockIdx.y;
    const size_t ro = (size_t)b * SS * SS + (size_t)q * SS;
    const float* row = g_p + ro;
    __nv_bfloat16* ph = g_ph + ro;
    __nv_bfloat16* pl = g_pl + ro;
    const int len = q + 1;
    const int kend = ((q >> 7) + 1) << 7;
    const int t = threadIdx.x;

    __shared__ float red[256];

    float m = -INFINITY;
    for (int k = t; k < len; k += 256) m = fmaxf(m, row[k]);
    red[t] = m; __syncthreads();
    for (int s = 128; s > 0; s >>= 1) {
        if (t < s) red[t] = fmaxf(red[t], red[t + s]);
        __syncthreads();
    }
    m = red[0];
    __syncthreads();

    float sum = 0.0f;
    for (int k = t; k < len; k += 256) sum += __expf(row[k] - m);
    red[t] = sum; __syncthreads();
    for (int s = 128; s > 0; s >>= 1) {
        if (t < s) red[t] += red[t + s];
        __syncthreads();
    }
    const float inv = 1.0f / red[0];

    for (int k = t; k < len; k += 256) {
        float w = __expf(row[k] - m) * inv;
        __nv_bfloat16 hh = __float2bfloat16(w);
        ph[k] = hh;
        pl[k] = __float2bfloat16(w - __bfloat162float(hh));
    }
    const __nv_bfloat16 z = __float2bfloat16(0.0f);
    for (int k = len + t; k < kend; k += 256) { ph[k] = z; pl[k] = z; }
}

// ---------------------------------------------------------------------------
// Output: O[b,q,e] = sum_k P[b,q,k] * Vt[b,e,k], K clamped to q-tile edge
// ---------------------------------------------------------------------------
__global__ __launch_bounds__(256, 1) void pv_kernel(float* __restrict__ out)
{
    extern __shared__ char smem[];
    const int b = blockIdx.z;
    const size_t q0 = (size_t)blockIdx.x * 128;
    const size_t e0 = (size_t)blockIdx.y * 128;
    const int nch = 2 * (blockIdx.x + 1);   // K = q0+128 in 64-chunks

    float C[16][4];
    gemm_tile(smem,
              g_ph + (size_t)b * SS * SS, g_pl + (size_t)b * SS * SS, q0, SS,
              g_vth + (size_t)b * DD * SS, g_vtl + (size_t)b * DD * SS, e0, SS,
              nch, C);

    FRAG_COORDS();
    #pragma unroll
    for (int am = 0; am < 4; am++) {
        #pragma unroll
        for (int n = 0; n < 4; n++) {
            const float* c = C[am * 4 + n];
            const int gr = wm * 64 + am * 16 + (lane >> 2);
            const int gc = (int)e0 + wn * 32 + n * 8 + (lane & 3) * 2;
            float2 v0 = make_float2(c[0], c[1]);
            float2 v1 = make_float2(c[2], c[3]);
            *(float2*)(out + ((size_t)b * SS + q0 + (size_t)gr) * DD + gc) = v0;
            *(float2*)(out + ((size_t)b * SS + q0 + (size_t)gr + 8) * DD + gc) = v1;
        }
    }
}

// ---------------------------------------------------------------------------
extern "C" void kernel_launch(void* const* d_in, const int* in_sizes, int n_in,
                              void* d_out, int out_size)
{
    const float* X  = (const float*)d_in[0];
    const float* Wq = (const float*)d_in[1];
    const float* Wk = (const float*)d_in[2];
    const float* Wv = (const float*)d_in[3];
    float* out      = (float*)d_out;

    static int attr_done = 0;
    if (!attr_done) {
        cudaFuncSetAttribute(proj_kernel,   cudaFuncAttributeMaxDynamicSharedMemorySize, SMEM_BYTES);
        cudaFuncSetAttribute(scores_kernel, cudaFuncAttributeMaxDynamicSharedMemorySize, SMEM_BYTES);
        cudaFuncSetAttribute(pv_kernel,     cudaFuncAttributeMaxDynamicSharedMemorySize, SMEM_BYTES);
        attr_done = 1;
    }

    {
        int n4 = (MM * DD) / 4;
        split_kernel<<<(n4 + 255) / 256, 256>>>(X, 0, n4);
        int w4 = (DD * DD) / 4;
        split_kernel<<<(w4 + 255) / 256, 256>>>(Wq, 1, w4);
        split_kernel<<<(w4 + 255) / 256, 256>>>(Wk, 2, w4);
        split_kernel<<<(w4 + 255) / 256, 256>>>(Wv, 3, w4);
    }

    dim3 g1(MM / 128, DD / 128, 3);
    proj_kernel<<<g1, 256, SMEM_BYTES>>>();

    dim3 g2(SS / 128, SS / 128, BB);
    scores_kernel<<<g2, 256, SMEM_BYTES>>>();

    dim3 g3(SS, BB);
    softmax_kernel<<<g3, 256>>>();

    dim3 g4(SS / 128, DD / 128, BB);
    pv_kernel<<<g4, 256, SMEM_BYTES>>>(out);
}

// round 6
// speedup vs baseline: 3.8315x; 1.0140x over previous
#include <cuda_runtime.h>
#include <cuda_bf16.h>
#include <cstdint>
#include <math.h>

#define BB 4
#define SS 4096
#define DD 1024
#define MM (BB * SS)   // 16384

// ---------------------------------------------------------------------------
// Scratch (__device__ globals; alloc-free rule)
// ---------------------------------------------------------------------------
__device__ __align__(256) __nv_bfloat16 g_xh[(size_t)MM * DD];
__device__ __align__(256) __nv_bfloat16 g_xl[(size_t)MM * DD];
__device__ __align__(256) __nv_bfloat16 g_wh[(size_t)3 * DD * DD];
__device__ __align__(256) __nv_bfloat16 g_wl[(size_t)3 * DD * DD];
__device__ __align__(256) __nv_bfloat16 g_qh[(size_t)MM * DD];
__device__ __align__(256) __nv_bfloat16 g_ql[(size_t)MM * DD];
__device__ __align__(256) __nv_bfloat16 g_kh[(size_t)MM * DD];
__device__ __align__(256) __nv_bfloat16 g_kl[(size_t)MM * DD];
__device__ __align__(256) __nv_bfloat16 g_vth[(size_t)MM * DD];  // [b][e][s]
__device__ __align__(256) __nv_bfloat16 g_vtl[(size_t)MM * DD];  // [b][e][s]
__device__ __align__(256) float         g_p [(size_t)BB * SS * SS]; // fp32 scores
__device__ __align__(256) __nv_bfloat16 g_ph[(size_t)BB * SS * SS]; // softmax hi
__device__ __align__(256) __nv_bfloat16 g_pl[(size_t)BB * SS * SS]; // softmax lo

// ---------------------------------------------------------------------------
// PTX helpers (sm_80-era PTX only: cp.async, ldmatrix, mma.sync)
// ---------------------------------------------------------------------------
__device__ __forceinline__ uint32_t smem_u32(const void* p) {
    uint32_t a;
    asm("{ .reg .u64 t; cvta.to.shared.u64 t, %1; cvt.u32.u64 %0, t; }"
        : "=r"(a) : "l"(p));
    return a;
}

#define LDSM4(r0, r1, r2, r3, addr) \
    asm volatile("ldmatrix.sync.aligned.m8n8.x4.shared.b16 {%0,%1,%2,%3}, [%4];" \
                 : "=r"(r0), "=r"(r1), "=r"(r2), "=r"(r3) : "r"(addr))

__device__ __forceinline__ void mma_bf16(float* c, const uint32_t* a,
                                         uint32_t b0, uint32_t b1) {
    asm volatile(
        "mma.sync.aligned.m16n8k16.row.col.f32.bf16.bf16.f32 "
        "{%0,%1,%2,%3}, {%4,%5,%6,%7}, {%8,%9}, {%0,%1,%2,%3};"
        : "+f"(c[0]), "+f"(c[1]), "+f"(c[2]), "+f"(c[3])
        : "r"(a[0]), "r"(a[1]), "r"(a[2]), "r"(a[3]), "r"(b0), "r"(b1));
}

template <int N>
__device__ __forceinline__ void cp_wait() {
    asm volatile("cp.async.wait_group %0;" :: "n"(N) : "memory");
}
__device__ __forceinline__ void cp_commit() {
    asm volatile("cp.async.commit_group;" ::: "memory");
}

// smem stage layout: 4 tiles of 128 rows x 64 bf16 (128B rows, SW128 swizzle)
#define TILE_SZ  16384
#define T_AH     0
#define T_AL     16384
#define T_BH     32768
#define T_BL     49152
#define STAGE_SZ 65536
#define NSTAGE   3
#define SMEM_BYTES (NSTAGE * STAGE_SZ)

__device__ __forceinline__ uint32_t sw_off(int r, int cbyte) {
    uint32_t off = (uint32_t)(r * 128 + cbyte);
    return off ^ ((off >> 3) & 0x70);
}

// Load one 128x64-bf16 tile (K-contiguous source) into swizzled smem via cp.async.
__device__ __forceinline__ void cp_tile(uint32_t sdst,
                                        const __nv_bfloat16* __restrict__ g,
                                        size_t row0, int ldk, int k0) {
    const int t = threadIdx.x;
    const char* gb = (const char*)(g + row0 * (size_t)ldk + (size_t)k0);
    #pragma unroll
    for (int i = 0; i < 4; i++) {
        int u = t + i * 256;            // 0..1023
        int r = u >> 3, cb = (u & 7) * 16;
        const char* src = gb + (size_t)r * (size_t)ldk * 2 + cb;
        asm volatile("cp.async.cg.shared.global [%0], [%1], 16;"
                     :: "r"(sdst + sw_off(r, cb)), "l"(src) : "memory");
    }
}

// ---------------------------------------------------------------------------
// Compute one BK=64 chunk: C += (Ah+Al)(128x64) @ (Bh+Bl)(128x64)^T (3 passes)
// ---------------------------------------------------------------------------
__device__ __forceinline__ void compute_chunk(uint32_t stage, float C[16][4]) {
    const int lane = threadIdx.x & 31;
    const int wid  = threadIdx.x >> 5;
    const int wm = wid & 1;   // 0/1: 64-row half
    const int wn = wid >> 1;  // 0..3: 32-col quarter

    uint32_t ah[4][4], al[4][4], bh[4][4], bl[4][4];

    #pragma unroll
    for (int ks = 0; ks < 4; ks++) {
        if ((ks & 1) == 0) {
            #pragma unroll
            for (int n = 0; n < 4; n++) {
                int r  = wn * 32 + n * 8 + (lane & 7);
                int cb = ks * 32 + (lane >> 3) * 16;
                uint32_t o = sw_off(r, cb);
                LDSM4(bh[n][0], bh[n][1], bh[n][2], bh[n][3], stage + T_BH + o);
                LDSM4(bl[n][0], bl[n][1], bl[n][2], bl[n][3], stage + T_BL + o);
            }
        }
        #pragma unroll
        for (int am = 0; am < 4; am++) {
            int r  = wm * 64 + am * 16 + (lane & 15);
            int cb = ks * 32 + (lane >> 4) * 16;
            uint32_t o = sw_off(r, cb);
            LDSM4(ah[am][0], ah[am][1], ah[am][2], ah[am][3], stage + T_AH + o);
            LDSM4(al[am][0], al[am][1], al[am][2], al[am][3], stage + T_AL + o);
        }
        const int kp = (ks & 1) * 2;
        #pragma unroll
        for (int am = 0; am < 4; am++) {
            #pragma unroll
            for (int n = 0; n < 4; n++) {
                float* c = C[am * 4 + n];
                mma_bf16(c, ah[am], bh[n][kp], bh[n][kp + 1]);
                mma_bf16(c, ah[am], bl[n][kp], bl[n][kp + 1]);
                mma_bf16(c, al[am], bh[n][kp], bh[n][kp + 1]);
            }
        }
    }
}

// ---------------------------------------------------------------------------
// 128x128 NT GEMM tile: C = (Ah+Al)[128,K] @ (Bh+Bl)[128,K]^T, K = nch*64
// 3-stage cp.async pipeline, ONE __syncthreads per chunk.
// ---------------------------------------------------------------------------
__device__ __forceinline__ void gemm_tile(
    char* smem,
    const __nv_bfloat16* __restrict__ Ah, const __nv_bfloat16* __restrict__ Al,
    size_t arow0, int lda,
    const __nv_bfloat16* __restrict__ Bh, const __nv_bfloat16* __restrict__ Bl,
    size_t brow0, int ldb,
    int nch, float C[16][4])
{
    const uint32_t sb = smem_u32(smem);

    #pragma unroll
    for (int i = 0; i < 16; i++)
        #pragma unroll
        for (int j = 0; j < 4; j++) C[i][j] = 0.0f;

    // prologue: stages 0, 1  (nch >= 2 always)
    cp_tile(sb + T_AH, Ah, arow0, lda, 0);
    cp_tile(sb + T_AL, Al, arow0, lda, 0);
    cp_tile(sb + T_BH, Bh, brow0, ldb, 0);
    cp_tile(sb + T_BL, Bl, brow0, ldb, 0);
    cp_commit();
    {
        const uint32_t ns = sb + STAGE_SZ;
        cp_tile(ns + T_AH, Ah, arow0, lda, 64);
        cp_tile(ns + T_AL, Al, arow0, lda, 64);
        cp_tile(ns + T_BH, Bh, brow0, ldb, 64);
        cp_tile(ns + T_BL, Bl, brow0, ldb, 64);
        cp_commit();
    }

    int st = 0;        // stage index of chunk c
    int st2 = 2;       // stage index of chunk c+2
    for (int c = 0; c < nch; c++) {
        if (c == nch - 1) cp_wait<0>(); else cp_wait<1>();
        __syncthreads();
        if (c + 2 < nch) {
            const uint32_t ns = sb + st2 * STAGE_SZ;
            const int k0 = (c + 2) * 64;
            cp_tile(ns + T_AH, Ah, arow0, lda, k0);
            cp_tile(ns + T_AL, Al, arow0, lda, k0);
            cp_tile(ns + T_BH, Bh, brow0, ldb, k0);
            cp_tile(ns + T_BL, Bl, brow0, ldb, k0);
            cp_commit();
        }
        compute_chunk(sb + st * STAGE_SZ, C);
        st  = (st  == NSTAGE - 1) ? 0 : st  + 1;
        st2 = (st2 == NSTAGE - 1) ? 0 : st2 + 1;
    }
}

// C fragment coords: rows gr, gr+8; cols gc, gc+1
#define FRAG_COORDS() \
    const int lane = threadIdx.x & 31; \
    const int wid  = threadIdx.x >> 5; \
    const int wm = wid & 1, wn = wid >> 1;

// ---------------------------------------------------------------------------
// One merged split kernel: fp32 -> bf16 hi/lo for X, Wq, Wk, Wv
// ---------------------------------------------------------------------------
#define X4 ((MM * DD) / 4)
#define W4 ((DD * DD) / 4)

__global__ __launch_bounds__(256) void split_all_kernel(
    const float* __restrict__ X, const float* __restrict__ Wq,
    const float* __restrict__ Wk, const float* __restrict__ Wv)
{
    int i = blockIdx.x * 256 + threadIdx.x;
    const float* src;
    __nv_bfloat16 *h, *l;
    size_t off;
    if (i < X4) {
        src = X; h = g_xh; l = g_xl; off = (size_t)i;
    } else {
        int j = i - X4;
        if (j >= 3 * W4) return;
        int w = j / W4;
        off = (size_t)(j - w * W4);
        src = (w == 0) ? Wq : (w == 1) ? Wk : Wv;
        h = g_wh + (size_t)w * DD * DD;
        l = g_wl + (size_t)w * DD * DD;
    }
    float4 v = ((const float4*)src)[off];
    __nv_bfloat16 h0 = __float2bfloat16(v.x), h1 = __float2bfloat16(v.y);
    __nv_bfloat16 h2 = __float2bfloat16(v.z), h3 = __float2bfloat16(v.w);
    __nv_bfloat162 a, b;
    a.x = h0; a.y = h1; b.x = h2; b.y = h3;
    ((__nv_bfloat162*)h)[2 * off] = a; ((__nv_bfloat162*)h)[2 * off + 1] = b;
    a.x = __float2bfloat16(v.x - __bfloat162float(h0));
    a.y = __float2bfloat16(v.y - __bfloat162float(h1));
    b.x = __float2bfloat16(v.z - __bfloat162float(h2));
    b.y = __float2bfloat16(v.w - __bfloat162float(h3));
    ((__nv_bfloat162*)l)[2 * off] = a; ((__nv_bfloat162*)l)[2 * off + 1] = b;
}

// ---------------------------------------------------------------------------
// Projection: z=0 Q, z=1 K (bf16 hi/lo out), z=2 V (transposed via smem)
// ---------------------------------------------------------------------------
__global__ __launch_bounds__(256, 1) void proj_kernel()
{
    extern __shared__ char smem[];
    const int z = blockIdx.z;
    const size_t m0 = (size_t)blockIdx.x * 128;
    const int n0 = blockIdx.y * 128;

    float C[16][4];
    gemm_tile(smem,
              g_xh, g_xl, m0, DD,
              g_wh + (size_t)z * DD * DD, g_wl + (size_t)z * DD * DD, (size_t)n0, DD,
              DD / 64, C);

    FRAG_COORDS();
    if (z < 2) {
        __nv_bfloat16* H = (z == 0) ? g_qh : g_kh;
        __nv_bfloat16* L = (z == 0) ? g_ql : g_kl;
        #pragma unroll
        for (int am = 0; am < 4; am++) {
            #pragma unroll
            for (int n = 0; n < 4; n++) {
                const float* c = C[am * 4 + n];
                const int gr = wm * 64 + am * 16 + (lane >> 2);
                const int gc = n0 + wn * 32 + n * 8 + (lane & 3) * 2;
                #pragma unroll
                for (int half = 0; half < 2; half++) {
                    float f0 = c[half * 2], f1 = c[half * 2 + 1];
                    __nv_bfloat16 h0 = __float2bfloat16(f0);
                    __nv_bfloat16 h1 = __float2bfloat16(f1);
                    __nv_bfloat162 hv, lv;
                    hv.x = h0; hv.y = h1;
                    lv.x = __float2bfloat16(f0 - __bfloat162float(h0));
                    lv.y = __float2bfloat16(f1 - __bfloat162float(h1));
                    size_t a = (m0 + (size_t)(gr + half * 8)) * DD + gc;
                    *(__nv_bfloat162*)(H + a) = hv;
                    *(__nv_bfloat162*)(L + a) = lv;
                }
            }
        }
    } else {
        // V: transpose through smem -> coalesced bf16 stores along s
        float (*sf)[132] = (float (*)[132])smem;
        __syncthreads();  // GEMM smem stages are dead; reuse as fp32 tile
        #pragma unroll
        for (int am = 0; am < 4; am++) {
            #pragma unroll
            for (int n = 0; n < 4; n++) {
                const float* c = C[am * 4 + n];
                const int gr  = wm * 64 + am * 16 + (lane >> 2);
                const int gcl = wn * 32 + n * 8 + (lane & 3) * 2;
                sf[gr][gcl]         = c[0];
                sf[gr][gcl + 1]     = c[1];
                sf[gr + 8][gcl]     = c[2];
                sf[gr + 8][gcl + 1] = c[3];
            }
        }
        __syncthreads();
        const int tid = threadIdx.x;
        const int e_l = tid >> 1;            // 0..127 local e column
        const int s0  = (tid & 1) * 64;      // half of the 128 s-rows
        const int b = (int)(m0 >> 12);
        const int sbase = (int)(m0 & (SS - 1));
        __align__(16) unsigned short hb[64], lb[64];
        #pragma unroll
        for (int j = 0; j < 64; j++) {
            float f = sf[s0 + j][e_l];
            __nv_bfloat16 hh = __float2bfloat16(f);
            __nv_bfloat16 ll = __float2bfloat16(f - __bfloat162float(hh));
            hb[j] = *(unsigned short*)&hh;
            lb[j] = *(unsigned short*)&ll;
        }
        size_t a = ((size_t)b * DD + n0 + e_l) * SS + sbase + s0;
        #pragma unroll
        for (int v = 0; v < 8; v++) {
            *(uint4*)(g_vth + a + v * 8) = *(uint4*)&hb[v * 8];
            *(uint4*)(g_vtl + a + v * 8) = *(uint4*)&lb[v * 8];
        }
    }
}

// ---------------------------------------------------------------------------
// Scores: P[b,q,k] = (Q.K)/32, causal tile skip
// ---------------------------------------------------------------------------
__global__ __launch_bounds__(256, 1) void scores_kernel()
{
    if (blockIdx.y > blockIdx.x) return;
    extern __shared__ char smem[];
    const int b = blockIdx.z;
    const size_t q0 = (size_t)blockIdx.x * 128;
    const size_t k0 = (size_t)blockIdx.y * 128;

    float C[16][4];
    gemm_tile(smem,
              g_qh + (size_t)b * SS * DD, g_ql + (size_t)b * SS * DD, q0, DD,
              g_kh + (size_t)b * SS * DD, g_kl + (size_t)b * SS * DD, k0, DD,
              DD / 64, C);

    FRAG_COORDS();
    float* P = g_p + (size_t)b * SS * SS;
    const float scale = 0.03125f;  // 1/sqrt(1024)
    #pragma unroll
    for (int am = 0; am < 4; am++) {
        #pragma unroll
        for (int n = 0; n < 4; n++) {
            const float* c = C[am * 4 + n];
            const int gr = wm * 64 + am * 16 + (lane >> 2);
            const int gc = (int)k0 + wn * 32 + n * 8 + (lane & 3) * 2;
            float2 v0 = make_float2(c[0] * scale, c[1] * scale);
            float2 v1 = make_float2(c[2] * scale, c[3] * scale);
            *(float2*)(P + (q0 + (size_t)gr) * SS + gc) = v0;
            *(float2*)(P + (q0 + (size_t)gr + 8) * SS + gc) = v1;
        }
    }
}

// ---------------------------------------------------------------------------
// Softmax over k in [0,q]: single online stats pass + write pass.
// Emit bf16 hi/lo weights; zero tail to 128-tile edge.
// ---------------------------------------------------------------------------
__global__ __launch_bounds__(256) void softmax_kernel()
{
    const int q = blockIdx.x;
    const int b = blockIdx.y;
    const size_t ro = (size_t)b * SS * SS + (size_t)q * SS;
    const float* row = g_p + ro;
    __nv_bfloat16* ph = g_ph + ro;
    __nv_bfloat16* pl = g_pl + ro;
    const int len = q + 1;
    const int kend = ((q >> 7) + 1) << 7;
    const int t = threadIdx.x;

    __shared__ float redm[256];
    __shared__ float reds[256];

    // online (max, sum) in one pass
    float m = -1e30f, s = 0.0f;
    for (int k = t; k < len; k += 256) {
        float x = row[k];
        if (x > m) { s = s * __expf(m - x) + 1.0f; m = x; }
        else       { s += __expf(x - m); }
    }
    redm[t] = m; reds[t] = s;
    __syncthreads();
    for (int st = 128; st > 0; st >>= 1) {
        if (t < st) {
            float m2 = redm[t + st], s2 = reds[t + st];
            float M = fmaxf(redm[t], m2);
            reds[t] = reds[t] * __expf(redm[t] - M) + s2 * __expf(m2 - M);
            redm[t] = M;
        }
        __syncthreads();
    }
    const float M = redm[0];
    const float inv = 1.0f / reds[0];

    for (int k = t; k < len; k += 256) {
        float w = __expf(row[k] - M) * inv;
        __nv_bfloat16 hh = __float2bfloat16(w);
        ph[k] = hh;
        pl[k] = __float2bfloat16(w - __bfloat162float(hh));
    }
    const __nv_bfloat16 z = __float2bfloat16(0.0f);
    for (int k = len + t; k < kend; k += 256) { ph[k] = z; pl[k] = z; }
}

// ---------------------------------------------------------------------------
// Output: O[b,q,e] = sum_k P[b,q,k] * Vt[b,e,k], K clamped to q-tile edge
// ---------------------------------------------------------------------------
__global__ __launch_bounds__(256, 1) void pv_kernel(float* __restrict__ out)
{
    extern __shared__ char smem[];
    const int b = blockIdx.z;
    const size_t q0 = (size_t)blockIdx.x * 128;
    const size_t e0 = (size_t)blockIdx.y * 128;
    const int nch = 2 * (blockIdx.x + 1);   // K = q0+128 in 64-chunks

    float C[16][4];
    gemm_tile(smem,
              g_ph + (size_t)b * SS * SS, g_pl + (size_t)b * SS * SS, q0, SS,
              g_vth + (size_t)b * DD * SS, g_vtl + (size_t)b * DD * SS, e0, SS,
              nch, C);

    FRAG_COORDS();
    #pragma unroll
    for (int am = 0; am < 4; am++) {
        #pragma unroll
        for (int n = 0; n < 4; n++) {
            const float* c = C[am * 4 + n];
            const int gr = wm * 64 + am * 16 + (lane >> 2);
            const int gc = (int)e0 + wn * 32 + n * 8 + (lane & 3) * 2;
            float2 v0 = make_float2(c[0], c[1]);
            float2 v1 = make_float2(c[2], c[3]);
            *(float2*)(out + ((size_t)b * SS + q0 + (size_t)gr) * DD + gc) = v0;
            *(float2*)(out + ((size_t)b * SS + q0 + (size_t)gr + 8) * DD + gc) = v1;
        }
    }
}

// ---------------------------------------------------------------------------
extern "C" void kernel_launch(void* const* d_in, const int* in_sizes, int n_in,
                              void* d_out, int out_size)
{
    const float* X  = (const float*)d_in[0];
    const float* Wq = (const float*)d_in[1];
    const float* Wk = (const float*)d_in[2];
    const float* Wv = (const float*)d_in[3];
    float* out      = (float*)d_out;

    static int attr_done = 0;
    if (!attr_done) {
        cudaFuncSetAttribute(proj_kernel,   cudaFuncAttributeMaxDynamicSharedMemorySize, SMEM_BYTES);
        cudaFuncSetAttribute(scores_kernel, cudaFuncAttributeMaxDynamicSharedMemorySize, SMEM_BYTES);
        cudaFuncSetAttribute(pv_kernel,     cudaFuncAttributeMaxDynamicSharedMemorySize, SMEM_BYTES);
        attr_done = 1;
    }

    {
        int total = X4 + 3 * W4;
        split_all_kernel<<<(total + 255) / 256, 256>>>(X, Wq, Wk, Wv);
    }

    dim3 g1(MM / 128, DD / 128, 3);
    proj_kernel<<<g1, 256, SMEM_BYTES>>>();

    dim3 g2(SS / 128, SS / 128, BB);
    scores_kernel<<<g2, 256, SMEM_BYTES>>>();

    dim3 g3(SS, BB);
    softmax_kernel<<<g3, 256>>>();

    dim3 g4(SS / 128, DD / 128, BB);
    pv_kernel<<<g4, 256, SMEM_BYTES>>>(out);
}